// round 13
// baseline (speedup 1.0000x reference)
#include <cuda_runtime.h>
#include <cstdint>
#include <math.h>

#define PTS 16384            // B*N
#define BBATCH 16
#define NPT 1024
#define KNN 20
#define NEDGE 327680         // PTS*KNN
#define SQC 0.1f             // sqrt(c), c=0.01
#define MAXNORM_F 9.96f      // (1-4e-3)/sqrt(c)
#define NEG_INF __int_as_float(0xff800000)
#define POS_INF __int_as_float(0x7f800000)

// ----------------------------- scratch (device globals) -----------------------------
__device__ float v6_xp1[PTS * 3];
__device__ float v6_pd[(size_t)BBATCH * NPT * NPT];        // 67 MB (reused both stages)
__device__ int   v6_idx1[NEDGE];
__device__ int   v6_idx2[NEDGE];
__device__ float v6_mob1[NEDGE * 3];
__device__ float v6_x1max[PTS * 64];
__device__ float v6_x1min[PTS * 64];
__device__ float v6_part1[2 * 64 * 1024];
__device__ float v6_bnp1[128];
__device__ float v6_x1[PTS * 64];
__device__ float v6_xx2[PTS];
__device__ float v6_xp2[PTS * 64];
__device__ float v6_hc2[PTS * 192];
__device__ float v6_mob2[(size_t)NEDGE * 64];              // 84 MB
__device__ float v6_h2[(size_t)NEDGE * 192];               // 252 MB
__device__ float v6_x2max[PTS * 192];
__device__ float v6_x2min[PTS * 192];
__device__ float v6_part2[2 * 192 * 1024];
__device__ float v6_bnp2[384];
__device__ float v6_x2[PTS * 192];
__device__ float v6_catbuf[PTS * 256];
__device__ float v6_h3[(size_t)PTS * 1024];                // 67 MB
__device__ float v6_c3max[PTS];
__device__ float v6_c3min[PTS];
__device__ float v6_c3sum[PTS];
__device__ float v6_c3sq[PTS];
__device__ float v6_feat3[PTS];
__device__ float v6_hf1[BBATCH * 512];
__device__ float v6_hf2[BBATCH * 256];
__device__ int   v6_flag;

// ----------------------------- stage 1: Poincare map (3-dim) -----------------------------
__global__ void v6_e2p1(const float* __restrict__ x) {
    int p = blockIdx.x * blockDim.x + threadIdx.x;
    if (p >= PTS) return;
    float a = x[p * 3 + 0], b = x[p * 3 + 1], c = x[p * 3 + 2];
    float n2 = a * a + b * b + c * c;
    float n = fmaxf(sqrtf(n2), 1e-15f);
    float s = tanhf(SQC * n) / (SQC * n);
    float ny = fmaxf(s * n, 1e-15f);
    float f = (ny > MAXNORM_F) ? (MAXNORM_F / ny) : 1.0f;
    s *= f;
    v6_xp1[p * 3 + 0] = a * s;
    v6_xp1[p * 3 + 1] = b * s;
    v6_xp1[p * 3 + 2] = c * s;
}

// ----------------------------- pairwise -dist^2, layer 1 (3-dim) -----------------------------
__global__ void v6_pd1(const float* __restrict__ x) {
    __shared__ float xs[NPT * 3];
    int row = blockIdx.x;
    int b = row >> 10, i = row & 1023;
    int t = threadIdx.x;
    const float* xb = x + (size_t)b * NPT * 3;
    for (int q = t; q < NPT * 3; q += 256) xs[q] = xb[q];
    __syncthreads();
    float xi0 = xs[i * 3], xi1 = xs[i * 3 + 1], xi2 = xs[i * 3 + 2];
    float xxi = xi0 * xi0 + xi1 * xi1 + xi2 * xi2;
    float* out = v6_pd + (size_t)row * NPT;
    for (int j = t; j < NPT; j += 256) {
        float a = xs[j * 3], bv = xs[j * 3 + 1], c = xs[j * 3 + 2];
        float xxj = a * a + bv * bv + c * c;
        float dot = xi0 * a + xi1 * bv + xi2 * c;
        out[j] = (2.0f * dot - xxi) - xxj;
    }
}

// ----------------------------- top-K selection (tie -> smaller index) -----------------------------
__global__ void v6_topk(int stage) {
    __shared__ float sd[NPT];
    __shared__ float rv[256];
    __shared__ int ri[256];
    int row = blockIdx.x;
    int b = row >> 10;
    int t = threadIdx.x;
    const float* src = v6_pd + (size_t)row * NPT;
    for (int j = t; j < NPT; j += 256) sd[j] = src[j];
    __syncthreads();
    int* idxout = (stage == 0) ? v6_idx1 : v6_idx2;
    for (int it = 0; it < KNN; it++) {
        float bv = NEG_INF;
        int bi = 1 << 30;
        for (int j = t; j < NPT; j += 256) {
            float v = sd[j];
            if (v > bv) { bv = v; bi = j; }
        }
        rv[t] = bv; ri[t] = bi;
        __syncthreads();
        for (int s = 128; s > 0; s >>= 1) {
            if (t < s) {
                float v2 = rv[t + s]; int i2 = ri[t + s];
                if (v2 > rv[t] || (v2 == rv[t] && i2 < ri[t])) { rv[t] = v2; ri[t] = i2; }
            }
            __syncthreads();
        }
        if (t == 0) {
            int sel = (ri[0] < NPT) ? ri[0] : 0;
            idxout[row * KNN + it] = (b << 10) + sel;
            sd[sel] = NEG_INF;
        }
        __syncthreads();
    }
}

// ----------------------------- mobius edge features, layer 1 -----------------------------
__global__ void v6_mobA() {
    int gid = blockIdx.x * blockDim.x + threadIdx.x;
    if (gid >= NEDGE) return;
    int p = gid / KNN;
    int jp = v6_idx1[gid];
    float c0 = v6_xp1[p * 3], c1 = v6_xp1[p * 3 + 1], c2 = v6_xp1[p * 3 + 2];
    float f0 = v6_xp1[jp * 3], f1 = v6_xp1[jp * 3 + 1], f2 = v6_xp1[jp * 3 + 2];
    float x2s = f0 * f0 + f1 * f1 + f2 * f2;
    float y2 = c0 * c0 + c1 * c1 + c2 * c2;
    float d = f0 * c0 + f1 * c1 + f2 * c2;
    float A = 1.0f - 0.02f * d + 0.01f * y2;
    float Bc = 1.0f - 0.01f * x2s;
    float den = fmaxf(1.0f - 0.02f * d + 1e-4f * x2s * y2, 1e-15f);
    float r = 1.0f / den;
    v6_mob1[gid * 3 + 0] = (A * f0 - Bc * c0) * r;
    v6_mob1[gid * 3 + 1] = (A * f1 - Bc * c1) * r;
    v6_mob1[gid * 3 + 2] = (A * f2 - Bc * c2) * r;
}

// ----------------------------- conv1 (64 x 6) + stats + max/min over k -----------------------------
__global__ void v6_conv1(const float* __restrict__ w) {
    __shared__ float mobS[16 * KNN * 3];
    __shared__ float xcS[16 * 3];
    int t = threadIdx.x;          // 0..63 = out channel
    int p0 = blockIdx.x * 16;
    for (int i = t; i < 16 * KNN * 3; i += 64) mobS[i] = v6_mob1[p0 * KNN * 3 + i];
    for (int i = t; i < 48; i += 64) xcS[i] = v6_xp1[p0 * 3 + i];
    __syncthreads();
    float w0 = w[t * 6], w1 = w[t * 6 + 1], w2 = w[t * 6 + 2];
    float w3 = w[t * 6 + 3], w4 = w[t * 6 + 4], w5 = w[t * 6 + 5];
    float s1 = 0.f, s2 = 0.f;
    for (int pl = 0; pl < 16; pl++) {
        float hc = w3 * xcS[pl * 3] + w4 * xcS[pl * 3 + 1] + w5 * xcS[pl * 3 + 2];
        float mx = NEG_INF, mn = POS_INF;
        const float* mp = &mobS[pl * KNN * 3];
        for (int k = 0; k < KNN; k++) {
            float h = hc + w0 * mp[k * 3] + w1 * mp[k * 3 + 1] + w2 * mp[k * 3 + 2];
            mx = fmaxf(mx, h); mn = fminf(mn, h);
            s1 += h; s2 += h * h;
        }
        v6_x1max[(p0 + pl) * 64 + t] = mx;
        v6_x1min[(p0 + pl) * 64 + t] = mn;
    }
    v6_part1[t * 1024 + blockIdx.x] = s1;
    v6_part1[64 * 1024 + t * 1024 + blockIdx.x] = s2;
}

__global__ void v6_bnred1() {
    int o = threadIdx.x;   // 64 threads
    float s1 = 0.f, s2 = 0.f;
    for (int i = 0; i < 1024; i++) {
        s1 += v6_part1[o * 1024 + i];
        s2 += v6_part1[64 * 1024 + o * 1024 + i];
    }
    v6_bnp1[o] = s1; v6_bnp1[64 + o] = s2;
}

__global__ void v6_fin1(const float* __restrict__ g, const float* __restrict__ be) {
    int idx = blockIdx.x * blockDim.x + threadIdx.x;
    if (idx >= PTS * 64) return;
    int o = idx & 63;
    float cnt = 327680.0f;
    float mean = v6_bnp1[o] / cnt;
    float var = fmaxf(v6_bnp1[64 + o] / cnt - mean * mean, 0.0f);
    float inv = rsqrtf(var + 1e-5f);
    float gm = g[o];
    float sel = (gm >= 0.f) ? v6_x1max[idx] : v6_x1min[idx];
    float v = (sel - mean) * inv * gm + be[o];
    v6_x1[idx] = fmaxf(v, 0.f);
}

// ----------------------------- e2p (64-dim) + xx2 -----------------------------
__global__ void v6_e2p2() {
    int p = blockIdx.x * 8 + (threadIdx.x >> 5);
    if (p >= PTS) return;
    int lane = threadIdx.x & 31;
    const float* xr = v6_x1 + p * 64;
    float v0 = xr[lane], v1 = xr[lane + 32];
    float s = v0 * v0 + v1 * v1;
    for (int o = 16; o > 0; o >>= 1) s += __shfl_xor_sync(0xffffffffu, s, o);
    if (lane == 0) v6_xx2[p] = s;
    float n = fmaxf(sqrtf(s), 1e-15f);
    float sc = tanhf(SQC * n) / (SQC * n);
    float ny = fmaxf(sc * n, 1e-15f);
    float f = (ny > MAXNORM_F) ? (MAXNORM_F / ny) : 1.0f;
    sc *= f;
    v6_xp2[p * 64 + lane] = v0 * sc;
    v6_xp2[p * 64 + lane + 32] = v1 * sc;
}

// ----------------------------- pairwise -dist^2, layer 2 (64-dim), tiled -----------------------------
__global__ void v6_pd2() {
    __shared__ float As[16][68];
    __shared__ float Bs[16][68];
    int tx = threadIdx.x, ty = threadIdx.y;
    int b = blockIdx.z;
    int m0 = blockIdx.y * 64, n0 = blockIdx.x * 64;
    const float* X = v6_x1 + (size_t)b * NPT * 64;
    int tid = ty * 16 + tx;
    int li = tid >> 4, lj = tid & 15;
    float acc[4][4] = {};
    for (int k0 = 0; k0 < 64; k0 += 16) {
#pragma unroll
        for (int r = 0; r < 4; r++) {
            int i = li + r * 16;
            As[lj][i] = X[(size_t)(m0 + i) * 64 + k0 + lj];
            Bs[lj][i] = X[(size_t)(n0 + i) * 64 + k0 + lj];
        }
        __syncthreads();
#pragma unroll
        for (int kk = 0; kk < 16; kk++) {
            float4 av = *(const float4*)&As[kk][tx * 4];
            float4 bv = *(const float4*)&Bs[kk][ty * 4];
            float a[4] = {av.x, av.y, av.z, av.w};
            float bb[4] = {bv.x, bv.y, bv.z, bv.w};
#pragma unroll
            for (int i = 0; i < 4; i++)
#pragma unroll
                for (int j = 0; j < 4; j++)
                    acc[i][j] = fmaf(a[i], bb[j], acc[i][j]);
        }
        __syncthreads();
    }
#pragma unroll
    for (int i = 0; i < 4; i++) {
        int mi = m0 + tx * 4 + i;
#pragma unroll
        for (int j = 0; j < 4; j++) {
            int nj = n0 + ty * 4 + j;
            float v = (2.0f * acc[i][j] - v6_xx2[b * NPT + mi]) - v6_xx2[b * NPT + nj];
            v6_pd[((size_t)(b * NPT + mi)) * NPT + nj] = v;
        }
    }
}

// ----------------------------- SGEMM body (device fn; A/C are device globals at call sites) ---------
static __device__ __forceinline__ void v6_gemm_body(
        const float* A, int lda, const float* Bw, int ldb,
        float* C, int ldc, int K, const float* hc, int hcDiv, int hcLd) {
    __shared__ float As[16][68];
    __shared__ float Bs[16][68];
    int tx = threadIdx.x, ty = threadIdx.y;
    int m0 = blockIdx.y * 64, n0 = blockIdx.x * 64;
    int tid = ty * 16 + tx;
    int li = tid >> 4, lj = tid & 15;
    float acc[4][4] = {};
    for (int k0 = 0; k0 < K; k0 += 16) {
#pragma unroll
        for (int r = 0; r < 4; r++) {
            int i = li + r * 16;
            As[lj][i] = A[(size_t)(m0 + i) * lda + k0 + lj];
            Bs[lj][i] = Bw[(size_t)(n0 + i) * ldb + k0 + lj];
        }
        __syncthreads();
#pragma unroll
        for (int kk = 0; kk < 16; kk++) {
            float4 av = *(const float4*)&As[kk][tx * 4];
            float4 bv = *(const float4*)&Bs[kk][ty * 4];
            float a[4] = {av.x, av.y, av.z, av.w};
            float bb[4] = {bv.x, bv.y, bv.z, bv.w};
#pragma unroll
            for (int i = 0; i < 4; i++)
#pragma unroll
                for (int j = 0; j < 4; j++)
                    acc[i][j] = fmaf(a[i], bb[j], acc[i][j]);
        }
        __syncthreads();
    }
#pragma unroll
    for (int i = 0; i < 4; i++) {
        int m = m0 + tx * 4 + i;
#pragma unroll
        for (int j = 0; j < 4; j++) {
            int n = n0 + ty * 4 + j;
            float v = acc[i][j];
            if (hc) v += hc[(size_t)(m / hcDiv) * hcLd + n];
            C[(size_t)m * ldc + n] = v;
        }
    }
}

// hc2[PTS x 192] = xp2 @ w2[:,64:]^T
__global__ void v6_gemm_hc2(const float* __restrict__ w2) {
    v6_gemm_body(v6_xp2, 64, w2 + 64, 128, v6_hc2, 192, 64, nullptr, 1, 0);
}
// h2[NEDGE x 192] = mob2 @ w2[:,0:64]^T + hc2[edge/20]
__global__ void v6_gemm_h2(const float* __restrict__ w2) {
    v6_gemm_body(v6_mob2, 64, w2, 128, v6_h2, 192, 64, v6_hc2, KNN, 192);
}
// h3[PTS x 1024] = catbuf @ conv3_w^T
__global__ void v6_gemm_h3(const float* __restrict__ w3) {
    v6_gemm_body(v6_catbuf, 256, w3, 256, v6_h3, 1024, 256, nullptr, 1, 0);
}

// ----------------------------- mobius edge features, layer 2 -----------------------------
__global__ void v6_mobB() {
    int g = blockIdx.x * 8 + (threadIdx.x >> 5);
    if (g >= NEDGE) return;
    int lane = threadIdx.x & 31;
    int p = g / KNN;
    int jp = v6_idx2[g];
    const float2* fx = (const float2*)(v6_xp2 + (size_t)jp * 64);
    const float2* cx = (const float2*)(v6_xp2 + (size_t)p * 64);
    float2 f = fx[lane], c2 = cx[lane];
    float x2s = f.x * f.x + f.y * f.y;
    float y2 = c2.x * c2.x + c2.y * c2.y;
    float d = f.x * c2.x + f.y * c2.y;
    for (int o = 16; o > 0; o >>= 1) {
        x2s += __shfl_xor_sync(0xffffffffu, x2s, o);
        y2 += __shfl_xor_sync(0xffffffffu, y2, o);
        d += __shfl_xor_sync(0xffffffffu, d, o);
    }
    float A = 1.0f - 0.02f * d + 0.01f * y2;
    float Bc = 1.0f - 0.01f * x2s;
    float den = fmaxf(1.0f - 0.02f * d + 1e-4f * x2s * y2, 1e-15f);
    float r = 1.0f / den;
    float2 o2;
    o2.x = (A * f.x - Bc * c2.x) * r;
    o2.y = (A * f.y - Bc * c2.y) * r;
    ((float2*)(v6_mob2 + (size_t)g * 64))[lane] = o2;
}

// ----------------------------- conv2 reduction over k + BN partials -----------------------------
__global__ void v6_red2() {
    int o = threadIdx.x;          // 0..191
    int p0 = blockIdx.x * 16;
    float s1 = 0.f, s2 = 0.f;
    for (int pl = 0; pl < 16; pl++) {
        float mx = NEG_INF, mn = POS_INF;
        size_t base = ((size_t)(p0 + pl) * KNN) * 192 + o;
        for (int k = 0; k < KNN; k++) {
            float v = v6_h2[base + (size_t)k * 192];
            mx = fmaxf(mx, v); mn = fminf(mn, v);
            s1 += v; s2 += v * v;
        }
        v6_x2max[(p0 + pl) * 192 + o] = mx;
        v6_x2min[(p0 + pl) * 192 + o] = mn;
    }
    v6_part2[o * 1024 + blockIdx.x] = s1;
    v6_part2[192 * 1024 + o * 1024 + blockIdx.x] = s2;
}

__global__ void v6_bnred2() {
    int o = threadIdx.x;   // 192 threads
    float s1 = 0.f, s2 = 0.f;
    for (int i = 0; i < 1024; i++) {
        s1 += v6_part2[o * 1024 + i];
        s2 += v6_part2[192 * 1024 + o * 1024 + i];
    }
    v6_bnp2[o] = s1; v6_bnp2[192 + o] = s2;
}

__global__ void v6_fin2(const float* __restrict__ g, const float* __restrict__ be) {
    int idx = blockIdx.x * blockDim.x + threadIdx.x;
    if (idx >= PTS * 192) return;
    int o = idx % 192;
    float cnt = 327680.0f;
    float mean = v6_bnp2[o] / cnt;
    float var = fmaxf(v6_bnp2[192 + o] / cnt - mean * mean, 0.0f);
    float inv = rsqrtf(var + 1e-5f);
    float gm = g[o];
    float sel = (gm >= 0.f) ? v6_x2max[idx] : v6_x2min[idx];
    float v = (sel - mean) * inv * gm + be[o];
    v6_x2[idx] = fmaxf(v, 0.f);
}

// ----------------------------- concat [x1, x2] -----------------------------
__global__ void v6_catk() {
    int idx = blockIdx.x * blockDim.x + threadIdx.x;
    if (idx >= PTS * 256) return;
    int p = idx >> 8, c = idx & 255;
    v6_catbuf[idx] = (c < 64) ? v6_x1[p * 64 + c] : v6_x2[p * 192 + c - 64];
}

// ----------------------------- conv3 reduction over N + BN partials -----------------------------
__global__ void v6_red3() {
    int o = blockIdx.x * 256 + threadIdx.x;
    int b = blockIdx.y;
    float mx = NEG_INF, mn = POS_INF, s1 = 0.f, s2 = 0.f;
    size_t base = ((size_t)b * NPT) * 1024 + o;
    for (int n = 0; n < NPT; n++) {
        float v = v6_h3[base + (size_t)n * 1024];
        mx = fmaxf(mx, v); mn = fminf(mn, v);
        s1 += v; s2 += v * v;
    }
    v6_c3max[b * 1024 + o] = mx;
    v6_c3min[b * 1024 + o] = mn;
    v6_c3sum[b * 1024 + o] = s1;
    v6_c3sq[b * 1024 + o] = s2;
}

__global__ void v6_fin3(const float* __restrict__ g, const float* __restrict__ be) {
    int idx = blockIdx.x * blockDim.x + threadIdx.x;
    if (idx >= PTS) return;
    int o = idx & 1023;
    float S1 = 0.f, S2 = 0.f;
    for (int bb = 0; bb < BBATCH; bb++) {
        S1 += v6_c3sum[bb * 1024 + o];
        S2 += v6_c3sq[bb * 1024 + o];
    }
    float cnt = 16384.0f;
    float mean = S1 / cnt;
    float var = fmaxf(S2 / cnt - mean * mean, 0.0f);
    float inv = rsqrtf(var + 1e-5f);
    float gm = g[o];
    float sel = (gm >= 0.f) ? v6_c3max[idx] : v6_c3min[idx];
    float v = (sel - mean) * inv * gm + be[o];
    v6_feat3[idx] = fmaxf(v, 0.f);
}

// ----------------------------- head: fc1 + LN + relu -----------------------------
__global__ void v6_fc1(const float* __restrict__ w, const float* __restrict__ bias,
                       const float* __restrict__ g, const float* __restrict__ be) {
    __shared__ float sIn[1024];
    __shared__ float sOut[512];
    __shared__ float red[256];
    int b = blockIdx.x, t = threadIdx.x;
    for (int i = t; i < 1024; i += 256) sIn[i] = v6_feat3[b * 1024 + i];
    __syncthreads();
    for (int r = 0; r < 2; r++) {
        int o = t + r * 256;
        float acc = bias[o];
        const float* wr = w + (size_t)o * 1024;
        for (int i = 0; i < 1024; i++) acc = fmaf(wr[i], sIn[i], acc);
        sOut[o] = acc;
    }
    __syncthreads();
    red[t] = sOut[t] + sOut[t + 256];
    __syncthreads();
    for (int s = 128; s > 0; s >>= 1) { if (t < s) red[t] += red[t + s]; __syncthreads(); }
    float mean = red[0] / 512.0f;
    __syncthreads();
    float d0 = sOut[t] - mean, d1 = sOut[t + 256] - mean;
    red[t] = d0 * d0 + d1 * d1;
    __syncthreads();
    for (int s = 128; s > 0; s >>= 1) { if (t < s) red[t] += red[t + s]; __syncthreads(); }
    float inv = rsqrtf(red[0] / 512.0f + 1e-5f);
    for (int r = 0; r < 2; r++) {
        int o = t + r * 256;
        float v = (sOut[o] - mean) * inv * g[o] + be[o];
        v6_hf1[b * 512 + o] = fmaxf(v, 0.f);
    }
}

// ----------------------------- head: fc2 + LN + relu -----------------------------
__global__ void v6_fc2(const float* __restrict__ w, const float* __restrict__ bias,
                       const float* __restrict__ g, const float* __restrict__ be) {
    __shared__ float sIn[512];
    __shared__ float sOut[256];
    __shared__ float red[256];
    int b = blockIdx.x, t = threadIdx.x;
    for (int i = t; i < 512; i += 256) sIn[i] = v6_hf1[b * 512 + i];
    __syncthreads();
    {
        float acc = bias[t];
        const float* wr = w + (size_t)t * 512;
        for (int i = 0; i < 512; i++) acc = fmaf(wr[i], sIn[i], acc);
        sOut[t] = acc;
    }
    __syncthreads();
    red[t] = sOut[t];
    __syncthreads();
    for (int s = 128; s > 0; s >>= 1) { if (t < s) red[t] += red[t + s]; __syncthreads(); }
    float mean = red[0] / 256.0f;
    __syncthreads();
    float d0 = sOut[t] - mean;
    red[t] = d0 * d0;
    __syncthreads();
    for (int s = 128; s > 0; s >>= 1) { if (t < s) red[t] += red[t + s]; __syncthreads(); }
    float inv = rsqrtf(red[0] / 256.0f + 1e-5f);
    float v = (sOut[t] - mean) * inv * g[t] + be[t];
    v6_hf2[b * 256 + t] = fmaxf(v, 0.f);
}

// ----------------------------- diagnostic scan: locate collapse/NaN -----------------------------
__global__ void v6_diag() {
    __shared__ int sflags[16];
    __shared__ float ssum[4];
    int t = threadIdx.x;  // 256 threads, single block
    if (t < 16) sflags[t] = 0;
    if (t < 4) ssum[t] = 0.f;
    __syncthreads();
    int f_bnp1 = 0, f_x1m = 0, f_bnp2 = 0, f_x2m = 0, f_c3 = 0, f_hf1n = 0;
    float a_x1 = 0.f, a_x2 = 0.f, a_f3 = 0.f, a_h2 = 0.f;
    for (int i = t; i < 128; i += 256) if (!isfinite(v6_bnp1[i])) f_bnp1 = 1;
    for (int i = t; i < 65536; i += 256) if (!isfinite(v6_x1max[i])) f_x1m = 1;
    for (int i = t; i < 65536; i += 256) a_x1 += fabsf(v6_x1[i]);
    for (int i = t; i < 384; i += 256) if (!isfinite(v6_bnp2[i])) f_bnp2 = 1;
    for (int i = t; i < 98304; i += 256) if (!isfinite(v6_x2max[i])) f_x2m = 1;
    for (int i = t; i < 98304; i += 256) a_x2 += fabsf(v6_x2[i]);
    for (int i = t; i < PTS; i += 256) { if (!isfinite(v6_c3max[i]) || !isfinite(v6_c3sum[i])) f_c3 = 1; a_f3 += fabsf(v6_feat3[i]); }
    for (int i = t; i < BBATCH * 512; i += 256) if (!isfinite(v6_hf1[i])) f_hf1n = 1;
    for (int i = t; i < BBATCH * 256; i += 256) a_h2 += fabsf(v6_hf2[i]);
    if (f_bnp1) atomicOr(&sflags[0], 1);
    if (f_x1m)  atomicOr(&sflags[1], 1);
    if (f_bnp2) atomicOr(&sflags[2], 1);
    if (f_x2m)  atomicOr(&sflags[3], 1);
    if (f_c3)   atomicOr(&sflags[4], 1);
    if (f_hf1n) atomicOr(&sflags[5], 1);
    atomicAdd(&ssum[0], a_x1);
    atomicAdd(&ssum[1], a_x2);
    atomicAdd(&ssum[2], a_f3);
    atomicAdd(&ssum[3], a_h2);
    __syncthreads();
    if (t == 0) {
        int fl = 0;
        if (sflags[0]) fl = 1;                 // NaN in conv1 BN sums
        else if (sflags[1]) fl = 2;            // NaN in x1max
        else if (ssum[0] == 0.f) fl = 3;       // x1 all zero
        else if (sflags[2]) fl = 5;            // NaN in conv2 BN sums
        else if (sflags[3]) fl = 6;            // NaN in x2max
        else if (ssum[1] == 0.f) fl = 7;       // x2 all zero
        else if (sflags[4]) fl = 8;            // NaN in conv3 reductions
        else if (ssum[2] == 0.f) fl = 9;       // feat3 all zero
        else if (sflags[5]) fl = 10;           // NaN in hf1
        else if (ssum[3] == 0.f) fl = 11;      // hf2 all zero
        v6_flag = fl;
    }
}

// ----------------------------- head: out proj + log_softmax (or diag override) -----------------------------
__global__ void v6_outp(const float* __restrict__ w, const float* __restrict__ bias,
                        float* __restrict__ out) {
    __shared__ float sIn[256];
    __shared__ float lg[40];
    __shared__ float mS, lS;
    int b = blockIdx.x, t = threadIdx.x;  // 64 threads
    for (int i = t; i < 256; i += 64) sIn[i] = v6_hf2[b * 256 + i];
    __syncthreads();
    if (t < 40) {
        float acc = bias[t];
        const float* wr = w + (size_t)t * 256;
        for (int i = 0; i < 256; i++) acc = fmaf(wr[i], sIn[i], acc);
        lg[t] = acc;
    }
    __syncthreads();
    if (t == 0) {
        float m = NEG_INF;
        for (int i = 0; i < 40; i++) m = fmaxf(m, lg[i]);
        float s = 0.f;
        for (int i = 0; i < 40; i++) s += expf(lg[i] - m);
        mS = m; lS = logf(s);
    }
    __syncthreads();
    int fl = v6_flag;
    if (t < 40) out[b * 40 + t] = (fl > 0) ? (float)fl * 50.0f : (lg[t] - mS - lS);
}

// ----------------------------- launch -----------------------------
extern "C" void kernel_launch(void* const* d_in, const int* in_sizes, int n_in,
                              void* d_out, int out_size) {
    const float* x       = (const float*)d_in[0];
    const float* conv1_w = (const float*)d_in[1];
    const float* bn1_g   = (const float*)d_in[2];
    const float* bn1_b   = (const float*)d_in[3];
    const float* conv2_w = (const float*)d_in[4];
    const float* bn2_g   = (const float*)d_in[5];
    const float* bn2_b   = (const float*)d_in[6];
    const float* conv3_w = (const float*)d_in[7];
    const float* bn3_g   = (const float*)d_in[8];
    const float* bn3_b   = (const float*)d_in[9];
    const float* fc1_w   = (const float*)d_in[10];
    const float* fc1_b   = (const float*)d_in[11];
    const float* ln1_g   = (const float*)d_in[12];
    const float* ln1_b   = (const float*)d_in[13];
    const float* fc2_w   = (const float*)d_in[14];
    const float* fc2_b   = (const float*)d_in[15];
    const float* ln2_g   = (const float*)d_in[16];
    const float* ln2_b   = (const float*)d_in[17];
    const float* out_w   = (const float*)d_in[18];
    const float* out_b   = (const float*)d_in[19];
    float* out = (float*)d_out;

    // stage 1: graph feature 1 + conv1
    v6_e2p1<<<64, 256>>>(x);
    v6_pd1<<<PTS, 256>>>(x);
    v6_topk<<<PTS, 256>>>(0);
    v6_mobA<<<(NEDGE + 255) / 256, 256>>>();
    v6_conv1<<<1024, 64>>>(conv1_w);
    v6_bnred1<<<1, 64>>>();
    v6_fin1<<<(PTS * 64) / 256, 256>>>(bn1_g, bn1_b);

    // stage 2: graph feature 2 + conv2
    v6_e2p2<<<PTS / 8, 256>>>();
    {
        dim3 g(16, 16, 16), blk(16, 16);
        v6_pd2<<<g, blk>>>();
    }
    v6_topk<<<PTS, 256>>>(1);
    {
        dim3 blk(16, 16);
        v6_gemm_hc2<<<dim3(3, PTS / 64), blk>>>(conv2_w);
    }
    v6_mobB<<<NEDGE / 8, 256>>>();
    {
        dim3 blk(16, 16);
        v6_gemm_h2<<<dim3(3, NEDGE / 64), blk>>>(conv2_w);
    }
    v6_red2<<<PTS / 16, 192>>>();
    v6_bnred2<<<1, 192>>>();
    v6_fin2<<<(PTS * 192) / 256, 256>>>(bn2_g, bn2_b);

    // stage 3: conv3 + global max
    v6_catk<<<(PTS * 256) / 256, 256>>>();
    {
        dim3 blk(16, 16);
        v6_gemm_h3<<<dim3(16, PTS / 64), blk>>>(conv3_w);
    }
    {
        dim3 g(4, BBATCH);
        v6_red3<<<g, 256>>>();
    }
    v6_fin3<<<PTS / 256, 256>>>(bn3_g, bn3_b);

    // head
    v6_fc1<<<BBATCH, 256>>>(fc1_w, fc1_b, ln1_g, ln1_b);
    v6_fc2<<<BBATCH, 256>>>(fc2_w, fc2_b, ln2_g, ln2_b);
    v6_diag<<<1, 256>>>();
    v6_outp<<<BBATCH, 64>>>(out_w, out_b, out);
}

// round 14
// speedup vs baseline: 1.4937x; 1.4937x over previous
#include <cuda_runtime.h>
#include <cstdint>
#include <math.h>

#define PTS 16384            // B*N
#define BBATCH 16
#define NPT 1024
#define KNN 20
#define NEDGE 327680         // PTS*KNN
#define SQC 0.1f             // sqrt(c), c=0.01
#define MAXNORM_F 9.96f      // (1-4e-3)/sqrt(c)
#define NEG_INF __int_as_float(0xff800000)
#define POS_INF __int_as_float(0x7f800000)

// ----------------------------- scratch (device globals) -----------------------------
__device__ float v7_xp1[PTS * 3];
__device__ float v7_pd[(size_t)BBATCH * NPT * NPT];        // 67 MB (reused both stages)
__device__ int   v7_idx1[NEDGE];
__device__ int   v7_idx2[NEDGE];
__device__ float v7_mob1[NEDGE * 3];
__device__ float v7_x1max[PTS * 64];
__device__ float v7_x1min[PTS * 64];
__device__ float v7_part1[2 * 64 * 1024];
__device__ float v7_bnp1[128];
__device__ float v7_x1[PTS * 64];
__device__ float v7_xx2[PTS];
__device__ float v7_xp2[PTS * 64];
__device__ float v7_hc2[PTS * 192];
__device__ float v7_mob2[(size_t)NEDGE * 64];              // 84 MB
__device__ float v7_h2[(size_t)NEDGE * 192];               // 252 MB
__device__ float v7_x2max[PTS * 192];
__device__ float v7_x2min[PTS * 192];
__device__ float v7_part2[2 * 192 * 1024];
__device__ float v7_bnp2[384];
__device__ float v7_x2[PTS * 192];
__device__ float v7_catbuf[PTS * 256];
__device__ float v7_h3[(size_t)PTS * 1024];                // 67 MB
__device__ float v7_c3max[PTS];
__device__ float v7_c3min[PTS];
__device__ float v7_c3sum[PTS];
__device__ float v7_c3sq[PTS];
__device__ float v7_feat3[PTS];
__device__ float v7_hf1[BBATCH * 512];
__device__ float v7_hf2[BBATCH * 256];

// ----------------------------- packed f32x2 FMA (sm_103a FFMA2) -----------------------------
static __device__ __forceinline__ unsigned long long v7_fma2(
        unsigned long long a, unsigned long long b, unsigned long long c) {
    unsigned long long d;
    asm("fma.rn.f32x2 %0, %1, %2, %3;" : "=l"(d) : "l"(a), "l"(b), "l"(c));
    return d;
}
union v7_u2f { unsigned long long u; float2 f; };

// ----------------------------- stage 1: Poincare map (3-dim) -----------------------------
__global__ void v7_e2p1(const float* __restrict__ x) {
    int p = blockIdx.x * blockDim.x + threadIdx.x;
    if (p >= PTS) return;
    float a = x[p * 3 + 0], b = x[p * 3 + 1], c = x[p * 3 + 2];
    float n2 = a * a + b * b + c * c;
    float n = fmaxf(sqrtf(n2), 1e-15f);
    float s = tanhf(SQC * n) / (SQC * n);
    float ny = fmaxf(s * n, 1e-15f);
    float f = (ny > MAXNORM_F) ? (MAXNORM_F / ny) : 1.0f;
    s *= f;
    v7_xp1[p * 3 + 0] = a * s;
    v7_xp1[p * 3 + 1] = b * s;
    v7_xp1[p * 3 + 2] = c * s;
}

// ----------------------------- pairwise -dist^2, layer 1 (3-dim) -----------------------------
__global__ void v7_pd1(const float* __restrict__ x) {
    __shared__ float xs[NPT * 3];
    int row = blockIdx.x;
    int b = row >> 10, i = row & 1023;
    int t = threadIdx.x;
    const float* xb = x + (size_t)b * NPT * 3;
    for (int q = t; q < NPT * 3; q += 256) xs[q] = xb[q];
    __syncthreads();
    float xi0 = xs[i * 3], xi1 = xs[i * 3 + 1], xi2 = xs[i * 3 + 2];
    float xxi = xi0 * xi0 + xi1 * xi1 + xi2 * xi2;
    float* out = v7_pd + (size_t)row * NPT;
    for (int j = t; j < NPT; j += 256) {
        float a = xs[j * 3], bv = xs[j * 3 + 1], c = xs[j * 3 + 2];
        float xxj = a * a + bv * bv + c * c;
        float dot = xi0 * a + xi1 * bv + xi2 * c;
        out[j] = (2.0f * dot - xxi) - xxj;
    }
}

// ----------------------------- top-K selection (register + shfl; tie -> smaller index) ------------
__global__ void v7_topk(int stage) {
    __shared__ float swv[8];
    __shared__ int swi[8];
    __shared__ int swin;
    int row = blockIdx.x;
    int b = row >> 10;
    int t = threadIdx.x;            // 256 threads
    int lane = t & 31, wid = t >> 5;
    const float* src = v7_pd + (size_t)row * NPT;
    float4 vv = *(const float4*)&src[t * 4];
    float v[4] = {vv.x, vv.y, vv.z, vv.w};
    int* idxout = stage ? v7_idx2 : v7_idx1;
    for (int it = 0; it < KNN; it++) {
        float bv = v[0]; int bq = 0;
        if (v[1] > bv) { bv = v[1]; bq = 1; }
        if (v[2] > bv) { bv = v[2]; bq = 2; }
        if (v[3] > bv) { bv = v[3]; bq = 3; }
        int bj = t * 4 + bq;
#pragma unroll
        for (int o = 16; o > 0; o >>= 1) {
            float ov = __shfl_xor_sync(0xffffffffu, bv, o);
            int oj = __shfl_xor_sync(0xffffffffu, bj, o);
            if (ov > bv || (ov == bv && oj < bj)) { bv = ov; bj = oj; }
        }
        if (lane == 0) { swv[wid] = bv; swi[wid] = bj; }
        __syncthreads();
        if (wid == 0) {
            float cv = (lane < 8) ? swv[lane] : NEG_INF;
            int cj = (lane < 8) ? swi[lane] : (1 << 30);
#pragma unroll
            for (int o = 4; o > 0; o >>= 1) {
                float ov = __shfl_xor_sync(0xffffffffu, cv, o);
                int oj = __shfl_xor_sync(0xffffffffu, cj, o);
                if (ov > cv || (ov == cv && oj < cj)) { cv = ov; cj = oj; }
            }
            if (lane == 0) { swin = cj; idxout[row * KNN + it] = (b << 10) + cj; }
        }
        __syncthreads();
        int wj = swin;
        if ((wj >> 2) == t) v[wj & 3] = NEG_INF;
        __syncthreads();
    }
}

// ----------------------------- mobius edge features, layer 1 -----------------------------
__global__ void v7_mobA() {
    int gid = blockIdx.x * blockDim.x + threadIdx.x;
    if (gid >= NEDGE) return;
    int p = gid / KNN;
    int jp = v7_idx1[gid];
    float c0 = v7_xp1[p * 3], c1 = v7_xp1[p * 3 + 1], c2 = v7_xp1[p * 3 + 2];
    float f0 = v7_xp1[jp * 3], f1 = v7_xp1[jp * 3 + 1], f2 = v7_xp1[jp * 3 + 2];
    float x2s = f0 * f0 + f1 * f1 + f2 * f2;
    float y2 = c0 * c0 + c1 * c1 + c2 * c2;
    float d = f0 * c0 + f1 * c1 + f2 * c2;
    float A = 1.0f - 0.02f * d + 0.01f * y2;
    float Bc = 1.0f - 0.01f * x2s;
    float den = fmaxf(1.0f - 0.02f * d + 1e-4f * x2s * y2, 1e-15f);
    float r = 1.0f / den;
    v7_mob1[gid * 3 + 0] = (A * f0 - Bc * c0) * r;
    v7_mob1[gid * 3 + 1] = (A * f1 - Bc * c1) * r;
    v7_mob1[gid * 3 + 2] = (A * f2 - Bc * c2) * r;
}

// ----------------------------- conv1 (64 x 6) + stats + max/min over k -----------------------------
__global__ void v7_conv1(const float* __restrict__ w) {
    __shared__ float mobS[16 * KNN * 3];
    __shared__ float xcS[16 * 3];
    int t = threadIdx.x;          // 0..63 = out channel
    int p0 = blockIdx.x * 16;
    for (int i = t; i < 16 * KNN * 3; i += 64) mobS[i] = v7_mob1[p0 * KNN * 3 + i];
    for (int i = t; i < 48; i += 64) xcS[i] = v7_xp1[p0 * 3 + i];
    __syncthreads();
    float w0 = w[t * 6], w1 = w[t * 6 + 1], w2 = w[t * 6 + 2];
    float w3 = w[t * 6 + 3], w4 = w[t * 6 + 4], w5 = w[t * 6 + 5];
    float s1 = 0.f, s2 = 0.f;
    for (int pl = 0; pl < 16; pl++) {
        float hc = w3 * xcS[pl * 3] + w4 * xcS[pl * 3 + 1] + w5 * xcS[pl * 3 + 2];
        float mx = NEG_INF, mn = POS_INF;
        const float* mp = &mobS[pl * KNN * 3];
        for (int k = 0; k < KNN; k++) {
            float h = hc + w0 * mp[k * 3] + w1 * mp[k * 3 + 1] + w2 * mp[k * 3 + 2];
            mx = fmaxf(mx, h); mn = fminf(mn, h);
            s1 += h; s2 += h * h;
        }
        v7_x1max[(p0 + pl) * 64 + t] = mx;
        v7_x1min[(p0 + pl) * 64 + t] = mn;
    }
    v7_part1[t * 1024 + blockIdx.x] = s1;
    v7_part1[64 * 1024 + t * 1024 + blockIdx.x] = s2;
}

__global__ void v7_bnred1() {
    int o = threadIdx.x;   // 64 threads
    float s1 = 0.f, s2 = 0.f;
    for (int i = 0; i < 1024; i++) {
        s1 += v7_part1[o * 1024 + i];
        s2 += v7_part1[64 * 1024 + o * 1024 + i];
    }
    v7_bnp1[o] = s1; v7_bnp1[64 + o] = s2;
}

__global__ void v7_fin1(const float* __restrict__ g, const float* __restrict__ be) {
    int idx = blockIdx.x * blockDim.x + threadIdx.x;
    if (idx >= PTS * 64) return;
    int o = idx & 63;
    float cnt = 327680.0f;
    float mean = v7_bnp1[o] / cnt;
    float var = fmaxf(v7_bnp1[64 + o] / cnt - mean * mean, 0.0f);
    float inv = rsqrtf(var + 1e-5f);
    float gm = g[o];
    float sel = (gm >= 0.f) ? v7_x1max[idx] : v7_x1min[idx];
    float v = (sel - mean) * inv * gm + be[o];
    v7_x1[idx] = fmaxf(v, 0.f);
}

// ----------------------------- e2p (64-dim) + xx2 -----------------------------
__global__ void v7_e2p2() {
    int p = blockIdx.x * 8 + (threadIdx.x >> 5);
    if (p >= PTS) return;
    int lane = threadIdx.x & 31;
    const float* xr = v7_x1 + p * 64;
    float v0 = xr[lane], v1 = xr[lane + 32];
    float s = v0 * v0 + v1 * v1;
    for (int o = 16; o > 0; o >>= 1) s += __shfl_xor_sync(0xffffffffu, s, o);
    if (lane == 0) v7_xx2[p] = s;
    float n = fmaxf(sqrtf(s), 1e-15f);
    float sc = tanhf(SQC * n) / (SQC * n);
    float ny = fmaxf(sc * n, 1e-15f);
    float f = (ny > MAXNORM_F) ? (MAXNORM_F / ny) : 1.0f;
    sc *= f;
    v7_xp2[p * 64 + lane] = v0 * sc;
    v7_xp2[p * 64 + lane + 32] = v1 * sc;
}

// ----------------------------- f32x2 SGEMM: C[m][n] = sum_k A[m][k]*B[n][k] -----------------------
// Tile 128(M) x 64(N), K-chunk 16, 256 threads, 8x4 microtile via diagonal/anti-diagonal FFMA2.
// MODE 0: plain   MODE 1: + hc[m/KNN][n]   MODE 2: pd epilogue (2*acc - xx[m] - xx[n])
template<int MODE>
static __device__ __forceinline__ void v7_gemm_body(
        const float* __restrict__ A, int lda,
        const float* __restrict__ Bw, int ldb,
        float* __restrict__ C, int ldc, int K,
        const float* __restrict__ hc,
        const float* __restrict__ xx) {
    __shared__ __align__(16) float As[16][128 + 4];
    __shared__ __align__(16) float BsN[16][64 + 4];
    __shared__ __align__(16) float BsS[16][64 + 4];
    int tid = threadIdx.x;
    int tx = tid & 15, ty = tid >> 4;
    int m0 = blockIdx.y * 128, n0 = blockIdx.x * 64;
    int lr = tid >> 2;          // 0..63
    int lc = tid & 3;           // k-float4 within chunk
    unsigned long long accD[4][2], accA[4][2];
#pragma unroll
    for (int p = 0; p < 4; p++)
#pragma unroll
        for (int q = 0; q < 2; q++) { accD[p][q] = 0ull; accA[p][q] = 0ull; }
    for (int k0 = 0; k0 < K; k0 += 16) {
#pragma unroll
        for (int h = 0; h < 2; h++) {
            int r = lr + h * 64;
            float4 av = *(const float4*)&A[(size_t)(m0 + r) * lda + k0 + lc * 4];
            As[lc * 4 + 0][r] = av.x; As[lc * 4 + 1][r] = av.y;
            As[lc * 4 + 2][r] = av.z; As[lc * 4 + 3][r] = av.w;
        }
        {
            int n = lr;
            float4 bv = *(const float4*)&Bw[(size_t)(n0 + n) * ldb + k0 + lc * 4];
            BsN[lc * 4 + 0][n] = bv.x; BsN[lc * 4 + 1][n] = bv.y;
            BsN[lc * 4 + 2][n] = bv.z; BsN[lc * 4 + 3][n] = bv.w;
            int ns = n ^ 1;
            BsS[lc * 4 + 0][ns] = bv.x; BsS[lc * 4 + 1][ns] = bv.y;
            BsS[lc * 4 + 2][ns] = bv.z; BsS[lc * 4 + 3][ns] = bv.w;
        }
        __syncthreads();
#pragma unroll
        for (int kk = 0; kk < 16; kk++) {
            ulonglong2 a01 = *(const ulonglong2*)&As[kk][ty * 8];
            ulonglong2 a23 = *(const ulonglong2*)&As[kk][ty * 8 + 4];
            ulonglong2 bn = *(const ulonglong2*)&BsN[kk][tx * 4];
            ulonglong2 bs = *(const ulonglong2*)&BsS[kk][tx * 4];
            unsigned long long A2[4] = {a01.x, a01.y, a23.x, a23.y};
            unsigned long long BN2[2] = {bn.x, bn.y};
            unsigned long long BS2[2] = {bs.x, bs.y};
#pragma unroll
            for (int p = 0; p < 4; p++) {
#pragma unroll
                for (int q = 0; q < 2; q++) {
                    accD[p][q] = v7_fma2(A2[p], BN2[q], accD[p][q]);
                    accA[p][q] = v7_fma2(A2[p], BS2[q], accA[p][q]);
                }
            }
        }
        __syncthreads();
    }
#pragma unroll
    for (int p = 0; p < 4; p++) {
        int r0 = m0 + ty * 8 + 2 * p, r1 = r0 + 1;
        int nb = n0 + tx * 4;
        float c0[4], c1[4];
#pragma unroll
        for (int q = 0; q < 2; q++) {
            v7_u2f d, a;
            d.u = accD[p][q]; a.u = accA[p][q];
            c0[2 * q + 0] = d.f.x;   // (r0, 2q)
            c0[2 * q + 1] = a.f.x;   // (r0, 2q+1)
            c1[2 * q + 0] = a.f.y;   // (r1, 2q)
            c1[2 * q + 1] = d.f.y;   // (r1, 2q+1)
        }
        if (MODE == 1) {
            const float* h0 = &hc[(size_t)(r0 / KNN) * 192 + nb];
            const float* h1 = &hc[(size_t)(r1 / KNN) * 192 + nb];
#pragma unroll
            for (int j = 0; j < 4; j++) { c0[j] += h0[j]; c1[j] += h1[j]; }
        }
        if (MODE == 2) {
            float xm0 = xx[r0], xm1 = xx[r1];
#pragma unroll
            for (int j = 0; j < 4; j++) {
                float xn = xx[nb + j];
                c0[j] = (2.0f * c0[j] - xm0) - xn;
                c1[j] = (2.0f * c1[j] - xm1) - xn;
            }
        }
        *(float4*)&C[(size_t)r0 * ldc + nb] = make_float4(c0[0], c0[1], c0[2], c0[3]);
        *(float4*)&C[(size_t)r1 * ldc + nb] = make_float4(c1[0], c1[1], c1[2], c1[3]);
    }
}

// hc2[PTS x 192] = xp2 @ w2[:,64:]^T
__global__ void __launch_bounds__(256) v7_gemm_hc2(const float* __restrict__ w2) {
    v7_gemm_body<0>(v7_xp2, 64, w2 + 64, 128, v7_hc2, 192, 64, nullptr, nullptr);
}
// h2[NEDGE x 192] = mob2 @ w2[:,0:64]^T + hc2[edge/20]
__global__ void __launch_bounds__(256) v7_gemm_h2(const float* __restrict__ w2) {
    v7_gemm_body<1>(v7_mob2, 64, w2, 128, v7_h2, 192, 64, v7_hc2, nullptr);
}
// h3[PTS x 1024] = catbuf @ conv3_w^T
__global__ void __launch_bounds__(256) v7_gemm_h3(const float* __restrict__ w3) {
    v7_gemm_body<0>(v7_catbuf, 256, w3, 256, v7_h3, 1024, 256, nullptr, nullptr);
}
// pd[b][m][n] = 2*(x1_b[m]·x1_b[n]) - xx[m] - xx[n]
__global__ void __launch_bounds__(256) v7_gemm_pd2() {
    int b = blockIdx.z;
    const float* Xb = v7_x1 + (size_t)b * NPT * 64;
    float* Cb = v7_pd + (size_t)b * NPT * NPT;
    const float* xxb = v7_xx2 + b * NPT;
    v7_gemm_body<2>(Xb, 64, Xb, 64, Cb, NPT, 64, nullptr, xxb);
}

// ----------------------------- mobius edge features, layer 2 -----------------------------
__global__ void v7_mobB() {
    int g = blockIdx.x * 8 + (threadIdx.x >> 5);
    if (g >= NEDGE) return;
    int lane = threadIdx.x & 31;
    int p = g / KNN;
    int jp = v7_idx2[g];
    const float2* fx = (const float2*)(v7_xp2 + (size_t)jp * 64);
    const float2* cx = (const float2*)(v7_xp2 + (size_t)p * 64);
    float2 f = fx[lane], c2 = cx[lane];
    float x2s = f.x * f.x + f.y * f.y;
    float y2 = c2.x * c2.x + c2.y * c2.y;
    float d = f.x * c2.x + f.y * c2.y;
    for (int o = 16; o > 0; o >>= 1) {
        x2s += __shfl_xor_sync(0xffffffffu, x2s, o);
        y2 += __shfl_xor_sync(0xffffffffu, y2, o);
        d += __shfl_xor_sync(0xffffffffu, d, o);
    }
    float A = 1.0f - 0.02f * d + 0.01f * y2;
    float Bc = 1.0f - 0.01f * x2s;
    float den = fmaxf(1.0f - 0.02f * d + 1e-4f * x2s * y2, 1e-15f);
    float r = 1.0f / den;
    float2 o2;
    o2.x = (A * f.x - Bc * c2.x) * r;
    o2.y = (A * f.y - Bc * c2.y) * r;
    ((float2*)(v7_mob2 + (size_t)g * 64))[lane] = o2;
}

// ----------------------------- conv2 reduction over k + BN partials -----------------------------
__global__ void v7_red2() {
    int o = threadIdx.x;          // 0..191
    int p0 = blockIdx.x * 16;
    float s1 = 0.f, s2 = 0.f;
    for (int pl = 0; pl < 16; pl++) {
        float mx = NEG_INF, mn = POS_INF;
        size_t base = ((size_t)(p0 + pl) * KNN) * 192 + o;
        for (int k = 0; k < KNN; k++) {
            float v = v7_h2[base + (size_t)k * 192];
            mx = fmaxf(mx, v); mn = fminf(mn, v);
            s1 += v; s2 += v * v;
        }
        v7_x2max[(p0 + pl) * 192 + o] = mx;
        v7_x2min[(p0 + pl) * 192 + o] = mn;
    }
    v7_part2[o * 1024 + blockIdx.x] = s1;
    v7_part2[192 * 1024 + o * 1024 + blockIdx.x] = s2;
}

__global__ void v7_bnred2() {
    int o = threadIdx.x;   // 192 threads
    float s1 = 0.f, s2 = 0.f;
    for (int i = 0; i < 1024; i++) {
        s1 += v7_part2[o * 1024 + i];
        s2 += v7_part2[192 * 1024 + o * 1024 + i];
    }
    v7_bnp2[o] = s1; v7_bnp2[192 + o] = s2;
}

__global__ void v7_fin2(const float* __restrict__ g, const float* __restrict__ be) {
    int idx = blockIdx.x * blockDim.x + threadIdx.x;
    if (idx >= PTS * 192) return;
    int o = idx % 192;
    float cnt = 327680.0f;
    float mean = v7_bnp2[o] / cnt;
    float var = fmaxf(v7_bnp2[192 + o] / cnt - mean * mean, 0.0f);
    float inv = rsqrtf(var + 1e-5f);
    float gm = g[o];
    float sel = (gm >= 0.f) ? v7_x2max[idx] : v7_x2min[idx];
    float v = (sel - mean) * inv * gm + be[o];
    v7_x2[idx] = fmaxf(v, 0.f);
}

// ----------------------------- concat [x1, x2] -----------------------------
__global__ void v7_catk() {
    int idx = blockIdx.x * blockDim.x + threadIdx.x;
    if (idx >= PTS * 256) return;
    int p = idx >> 8, c = idx & 255;
    v7_catbuf[idx] = (c < 64) ? v7_x1[p * 64 + c] : v7_x2[p * 192 + c - 64];
}

// ----------------------------- conv3 reduction over N + BN partials -----------------------------
__global__ void v7_red3() {
    int o = blockIdx.x * 256 + threadIdx.x;
    int b = blockIdx.y;
    float mx = NEG_INF, mn = POS_INF, s1 = 0.f, s2 = 0.f;
    size_t base = ((size_t)b * NPT) * 1024 + o;
    for (int n = 0; n < NPT; n++) {
        float v = v7_h3[base + (size_t)n * 1024];
        mx = fmaxf(mx, v); mn = fminf(mn, v);
        s1 += v; s2 += v * v;
    }
    v7_c3max[b * 1024 + o] = mx;
    v7_c3min[b * 1024 + o] = mn;
    v7_c3sum[b * 1024 + o] = s1;
    v7_c3sq[b * 1024 + o] = s2;
}

__global__ void v7_fin3(const float* __restrict__ g, const float* __restrict__ be) {
    int idx = blockIdx.x * blockDim.x + threadIdx.x;
    if (idx >= PTS) return;
    int o = idx & 1023;
    float S1 = 0.f, S2 = 0.f;
    for (int bb = 0; bb < BBATCH; bb++) {
        S1 += v7_c3sum[bb * 1024 + o];
        S2 += v7_c3sq[bb * 1024 + o];
    }
    float cnt = 16384.0f;
    float mean = S1 / cnt;
    float var = fmaxf(S2 / cnt - mean * mean, 0.0f);
    float inv = rsqrtf(var + 1e-5f);
    float gm = g[o];
    float sel = (gm >= 0.f) ? v7_c3max[idx] : v7_c3min[idx];
    float v = (sel - mean) * inv * gm + be[o];
    v7_feat3[idx] = fmaxf(v, 0.f);
}

// ----------------------------- head: fc1 + LN + relu -----------------------------
__global__ void v7_fc1(const float* __restrict__ w, const float* __restrict__ bias,
                       const float* __restrict__ g, const float* __restrict__ be) {
    __shared__ float sIn[1024];
    __shared__ float sOut[512];
    __shared__ float red[256];
    int b = blockIdx.x, t = threadIdx.x;
    for (int i = t; i < 1024; i += 256) sIn[i] = v7_feat3[b * 1024 + i];
    __syncthreads();
    for (int r = 0; r < 2; r++) {
        int o = t + r * 256;
        float acc = bias[o];
        const float* wr = w + (size_t)o * 1024;
        for (int i = 0; i < 1024; i++) acc = fmaf(wr[i], sIn[i], acc);
        sOut[o] = acc;
    }
    __syncthreads();
    red[t] = sOut[t] + sOut[t + 256];
    __syncthreads();
    for (int s = 128; s > 0; s >>= 1) { if (t < s) red[t] += red[t + s]; __syncthreads(); }
    float mean = red[0] / 512.0f;
    __syncthreads();
    float d0 = sOut[t] - mean, d1 = sOut[t + 256] - mean;
    red[t] = d0 * d0 + d1 * d1;
    __syncthreads();
    for (int s = 128; s > 0; s >>= 1) { if (t < s) red[t] += red[t + s]; __syncthreads(); }
    float inv = rsqrtf(red[0] / 512.0f + 1e-5f);
    for (int r = 0; r < 2; r++) {
        int o = t + r * 256;
        float v = (sOut[o] - mean) * inv * g[o] + be[o];
        v7_hf1[b * 512 + o] = fmaxf(v, 0.f);
    }
}

// ----------------------------- head: fc2 + LN + relu -----------------------------
__global__ void v7_fc2(const float* __restrict__ w, const float* __restrict__ bias,
                       const float* __restrict__ g, const float* __restrict__ be) {
    __shared__ float sIn[512];
    __shared__ float sOut[256];
    __shared__ float red[256];
    int b = blockIdx.x, t = threadIdx.x;
    for (int i = t; i < 512; i += 256) sIn[i] = v7_hf1[b * 512 + i];
    __syncthreads();
    {
        float acc = bias[t];
        const float* wr = w + (size_t)t * 512;
        for (int i = 0; i < 512; i++) acc = fmaf(wr[i], sIn[i], acc);
        sOut[t] = acc;
    }
    __syncthreads();
    red[t] = sOut[t];
    __syncthreads();
    for (int s = 128; s > 0; s >>= 1) { if (t < s) red[t] += red[t + s]; __syncthreads(); }
    float mean = red[0] / 256.0f;
    __syncthreads();
    float d0 = sOut[t] - mean;
    red[t] = d0 * d0;
    __syncthreads();
    for (int s = 128; s > 0; s >>= 1) { if (t < s) red[t] += red[t + s]; __syncthreads(); }
    float inv = rsqrtf(red[0] / 256.0f + 1e-5f);
    float v = (sOut[t] - mean) * inv * g[t] + be[t];
    v7_hf2[b * 256 + t] = fmaxf(v, 0.f);
}

// ----------------------------- head: out proj + log_softmax -----------------------------
__global__ void v7_outp(const float* __restrict__ w, const float* __restrict__ bias,
                        float* __restrict__ out) {
    __shared__ float sIn[256];
    __shared__ float lg[40];
    __shared__ float mS, lS;
    int b = blockIdx.x, t = threadIdx.x;  // 64 threads
    for (int i = t; i < 256; i += 64) sIn[i] = v7_hf2[b * 256 + i];
    __syncthreads();
    if (t < 40) {
        float acc = bias[t];
        const float* wr = w + (size_t)t * 256;
        for (int i = 0; i < 256; i++) acc = fmaf(wr[i], sIn[i], acc);
        lg[t] = acc;
    }
    __syncthreads();
    if (t == 0) {
        float m = NEG_INF;
        for (int i = 0; i < 40; i++) m = fmaxf(m, lg[i]);
        float s = 0.f;
        for (int i = 0; i < 40; i++) s += expf(lg[i] - m);
        mS = m; lS = logf(s);
    }
    __syncthreads();
    if (t < 40) out[b * 40 + t] = lg[t] - mS - lS;
}

// ----------------------------- launch -----------------------------
extern "C" void kernel_launch(void* const* d_in, const int* in_sizes, int n_in,
                              void* d_out, int out_size) {
    const float* x       = (const float*)d_in[0];
    const float* conv1_w = (const float*)d_in[1];
    const float* bn1_g   = (const float*)d_in[2];
    const float* bn1_b   = (const float*)d_in[3];
    const float* conv2_w = (const float*)d_in[4];
    const float* bn2_g   = (const float*)d_in[5];
    const float* bn2_b   = (const float*)d_in[6];
    const float* conv3_w = (const float*)d_in[7];
    const float* bn3_g   = (const float*)d_in[8];
    const float* bn3_b   = (const float*)d_in[9];
    const float* fc1_w   = (const float*)d_in[10];
    const float* fc1_b   = (const float*)d_in[11];
    const float* ln1_g   = (const float*)d_in[12];
    const float* ln1_b   = (const float*)d_in[13];
    const float* fc2_w   = (const float*)d_in[14];
    const float* fc2_b   = (const float*)d_in[15];
    const float* ln2_g   = (const float*)d_in[16];
    const float* ln2_b   = (const float*)d_in[17];
    const float* out_w   = (const float*)d_in[18];
    const float* out_b   = (const float*)d_in[19];
    float* out = (float*)d_out;

    // stage 1: graph feature 1 + conv1
    v7_e2p1<<<64, 256>>>(x);
    v7_pd1<<<PTS, 256>>>(x);
    v7_topk<<<PTS, 256>>>(0);
    v7_mobA<<<(NEDGE + 255) / 256, 256>>>();
    v7_conv1<<<1024, 64>>>(conv1_w);
    v7_bnred1<<<1, 64>>>();
    v7_fin1<<<(PTS * 64) / 256, 256>>>(bn1_g, bn1_b);

    // stage 2: graph feature 2 + conv2
    v7_e2p2<<<PTS / 8, 256>>>();
    v7_gemm_pd2<<<dim3(16, 8, 16), 256>>>();
    v7_topk<<<PTS, 256>>>(1);
    v7_gemm_hc2<<<dim3(3, PTS / 128), 256>>>(conv2_w);
    v7_mobB<<<NEDGE / 8, 256>>>();
    v7_gemm_h2<<<dim3(3, NEDGE / 128), 256>>>(conv2_w);
    v7_red2<<<PTS / 16, 192>>>();
    v7_bnred2<<<1, 192>>>();
    v7_fin2<<<(PTS * 192) / 256, 256>>>(bn2_g, bn2_b);

    // stage 3: conv3 + global max
    v7_catk<<<(PTS * 256) / 256, 256>>>();
    v7_gemm_h3<<<dim3(16, PTS / 128), 256>>>(conv3_w);
    v7_red3<<<dim3(4, BBATCH), 256>>>();
    v7_fin3<<<PTS / 256, 256>>>(bn3_g, bn3_b);

    // head
    v7_fc1<<<BBATCH, 256>>>(fc1_w, fc1_b, ln1_g, ln1_b);
    v7_fc2<<<BBATCH, 256>>>(fc2_w, fc2_b, ln2_g, ln2_b);
    v7_outp<<<BBATCH, 64>>>(out_w, out_b, out);
}

// round 16
// speedup vs baseline: 1.7463x; 1.1691x over previous
#include <cuda_runtime.h>
#include <cstdint>
#include <math.h>

#define PTS 16384            // B*N
#define BBATCH 16
#define NPT 1024
#define KNN 20
#define NEDGE 327680         // PTS*KNN
#define SQC 0.1f
#define MAXNORM_F 9.96f
#define NEG_INF __int_as_float(0xff800000)
#define POS_INF __int_as_float(0x7f800000)
#define H2TILES 2560         // NEDGE/128
#define H3TILES 128          // PTS/128

// ----------------------------- scratch (device globals) -----------------------------
__device__ float v8_xp1[PTS * 3];
__device__ float v8_pd[(size_t)BBATCH * NPT * NPT];
__device__ int   v8_idx1[NEDGE];
__device__ int   v8_idx2[NEDGE];
__device__ float v8_mob1[NEDGE * 3];
__device__ float v8_x1max[PTS * 64];
__device__ float v8_x1min[PTS * 64];
__device__ float v8_part1[2 * 64 * 1024];
__device__ float v8_bnp1[128];
__device__ float v8_x1[PTS * 64];
__device__ float v8_xx2[PTS];
__device__ float v8_xp2[PTS * 64];
__device__ float v8_hc2[PTS * 192];
__device__ float v8_mob2[(size_t)NEDGE * 64];
__device__ int   v8_x2maxI[PTS * 192];
__device__ int   v8_x2minI[PTS * 192];
__device__ float v8_p2s1[192 * H2TILES];
__device__ float v8_p2s2[192 * H2TILES];
__device__ float v8_bnp2[384];
__device__ float v8_x2[PTS * 192];
__device__ int   v8_c3maxI[BBATCH * 1024];
__device__ int   v8_c3minI[BBATCH * 1024];
__device__ float v8_p3s1[1024 * H3TILES];
__device__ float v8_p3s2[1024 * H3TILES];
__device__ float v8_bnp3[2048];
__device__ float v8_feat3[PTS];
__device__ float v8_hf1[BBATCH * 512];
__device__ float v8_hf2[BBATCH * 256];

// ----------------------------- helpers -----------------------------
static __device__ __forceinline__ unsigned long long v8_fma2(
        unsigned long long a, unsigned long long b, unsigned long long c) {
    unsigned long long d;
    asm("fma.rn.f32x2 %0, %1, %2, %3;" : "=l"(d) : "l"(a), "l"(b), "l"(c));
    return d;
}
union v8_u2f { unsigned long long u; float2 f; };
// monotone float<->int key (max/min via integer atomics)
static __device__ __forceinline__ int v8_fenc(float f) {
    int i = __float_as_int(f);
    return i >= 0 ? i : (i ^ 0x7FFFFFFF);
}
static __device__ __forceinline__ float v8_fdec(int i) {
    return __int_as_float(i >= 0 ? i : (i ^ 0x7FFFFFFF));
}

// ----------------------------- init encoded max/min buffers -----------------------------
__global__ void v8_init() {
    int idx = blockIdx.x * 256 + threadIdx.x;
    if (idx < PTS * 192) { v8_x2maxI[idx] = (int)0x80000000; v8_x2minI[idx] = 0x7FFFFFFF; }
    if (idx < BBATCH * 1024) { v8_c3maxI[idx] = (int)0x80000000; v8_c3minI[idx] = 0x7FFFFFFF; }
}

// ----------------------------- stage 1: Poincare map (3-dim) -----------------------------
__global__ void v8_e2p1(const float* __restrict__ x) {
    int p = blockIdx.x * blockDim.x + threadIdx.x;
    if (p >= PTS) return;
    float a = x[p * 3 + 0], b = x[p * 3 + 1], c = x[p * 3 + 2];
    float n2 = a * a + b * b + c * c;
    float n = fmaxf(sqrtf(n2), 1e-15f);
    float s = tanhf(SQC * n) / (SQC * n);
    float ny = fmaxf(s * n, 1e-15f);
    float f = (ny > MAXNORM_F) ? (MAXNORM_F / ny) : 1.0f;
    s *= f;
    v8_xp1[p * 3 + 0] = a * s;
    v8_xp1[p * 3 + 1] = b * s;
    v8_xp1[p * 3 + 2] = c * s;
}

// ----------------------------- pairwise -dist^2, layer 1 -----------------------------
__global__ void v8_pd1(const float* __restrict__ x) {
    __shared__ float xs[NPT * 3];
    int row = blockIdx.x;
    int b = row >> 10, i = row & 1023;
    int t = threadIdx.x;
    const float* xb = x + (size_t)b * NPT * 3;
    for (int q = t; q < NPT * 3; q += 256) xs[q] = xb[q];
    __syncthreads();
    float xi0 = xs[i * 3], xi1 = xs[i * 3 + 1], xi2 = xs[i * 3 + 2];
    float xxi = xi0 * xi0 + xi1 * xi1 + xi2 * xi2;
    float* out = v8_pd + (size_t)row * NPT;
    for (int j = t; j < NPT; j += 256) {
        float a = xs[j * 3], bv = xs[j * 3 + 1], c = xs[j * 3 + 2];
        float xxj = a * a + bv * bv + c * c;
        float dot = xi0 * a + xi1 * bv + xi2 * c;
        out[j] = (2.0f * dot - xxi) - xxj;
    }
}

// ----------------------------- top-K (register + shfl; tie -> smaller index) ---------------
__global__ void v8_topk(int stage) {
    __shared__ float swv[8];
    __shared__ int swi[8];
    __shared__ int swin;
    int row = blockIdx.x;
    int b = row >> 10;
    int t = threadIdx.x;
    int lane = t & 31, wid = t >> 5;
    const float* src = v8_pd + (size_t)row * NPT;
    float4 vv = *(const float4*)&src[t * 4];
    float v[4] = {vv.x, vv.y, vv.z, vv.w};
    int* idxout = stage ? v8_idx2 : v8_idx1;
    for (int it = 0; it < KNN; it++) {
        float bv = v[0]; int bq = 0;
        if (v[1] > bv) { bv = v[1]; bq = 1; }
        if (v[2] > bv) { bv = v[2]; bq = 2; }
        if (v[3] > bv) { bv = v[3]; bq = 3; }
        int bj = t * 4 + bq;
#pragma unroll
        for (int o = 16; o > 0; o >>= 1) {
            float ov = __shfl_xor_sync(0xffffffffu, bv, o);
            int oj = __shfl_xor_sync(0xffffffffu, bj, o);
            if (ov > bv || (ov == bv && oj < bj)) { bv = ov; bj = oj; }
        }
        if (lane == 0) { swv[wid] = bv; swi[wid] = bj; }
        __syncthreads();
        if (wid == 0) {
            float cv = (lane < 8) ? swv[lane] : NEG_INF;
            int cj = (lane < 8) ? swi[lane] : (1 << 30);
#pragma unroll
            for (int o = 4; o > 0; o >>= 1) {
                float ov = __shfl_xor_sync(0xffffffffu, cv, o);
                int oj = __shfl_xor_sync(0xffffffffu, cj, o);
                if (ov > cv || (ov == cv && oj < cj)) { cv = ov; cj = oj; }
            }
            if (lane == 0) { swin = cj; idxout[row * KNN + it] = (b << 10) + cj; }
        }
        __syncthreads();
        int wj = swin;
        if ((wj >> 2) == t) v[wj & 3] = NEG_INF;   // register-local; no barrier needed
    }
}

// ----------------------------- mobius edge features, layer 1 -----------------------------
__global__ void v8_mobA() {
    int gid = blockIdx.x * blockDim.x + threadIdx.x;
    if (gid >= NEDGE) return;
    int p = gid / KNN;
    int jp = v8_idx1[gid];
    float c0 = v8_xp1[p * 3], c1 = v8_xp1[p * 3 + 1], c2 = v8_xp1[p * 3 + 2];
    float f0 = v8_xp1[jp * 3], f1 = v8_xp1[jp * 3 + 1], f2 = v8_xp1[jp * 3 + 2];
    float x2s = f0 * f0 + f1 * f1 + f2 * f2;
    float y2 = c0 * c0 + c1 * c1 + c2 * c2;
    float d = f0 * c0 + f1 * c1 + f2 * c2;
    float A = 1.0f - 0.02f * d + 0.01f * y2;
    float Bc = 1.0f - 0.01f * x2s;
    float den = fmaxf(1.0f - 0.02f * d + 1e-4f * x2s * y2, 1e-15f);
    float r = 1.0f / den;
    v8_mob1[gid * 3 + 0] = (A * f0 - Bc * c0) * r;
    v8_mob1[gid * 3 + 1] = (A * f1 - Bc * c1) * r;
    v8_mob1[gid * 3 + 2] = (A * f2 - Bc * c2) * r;
}

// ----------------------------- conv1 (64 x 6) + stats + max/min over k ---------------------
__global__ void v8_conv1(const float* __restrict__ w) {
    __shared__ float mobS[16 * KNN * 3];
    __shared__ float xcS[16 * 3];
    int t = threadIdx.x;
    int p0 = blockIdx.x * 16;
    for (int i = t; i < 16 * KNN * 3; i += 64) mobS[i] = v8_mob1[p0 * KNN * 3 + i];
    for (int i = t; i < 48; i += 64) xcS[i] = v8_xp1[p0 * 3 + i];
    __syncthreads();
    float w0 = w[t * 6], w1 = w[t * 6 + 1], w2 = w[t * 6 + 2];
    float w3 = w[t * 6 + 3], w4 = w[t * 6 + 4], w5 = w[t * 6 + 5];
    float s1 = 0.f, s2 = 0.f;
    for (int pl = 0; pl < 16; pl++) {
        float hc = w3 * xcS[pl * 3] + w4 * xcS[pl * 3 + 1] + w5 * xcS[pl * 3 + 2];
        float mx = NEG_INF, mn = POS_INF;
        const float* mp = &mobS[pl * KNN * 3];
        for (int k = 0; k < KNN; k++) {
            float h = hc + w0 * mp[k * 3] + w1 * mp[k * 3 + 1] + w2 * mp[k * 3 + 2];
            mx = fmaxf(mx, h); mn = fminf(mn, h);
            s1 += h; s2 += h * h;
        }
        v8_x1max[(p0 + pl) * 64 + t] = mx;
        v8_x1min[(p0 + pl) * 64 + t] = mn;
    }
    v8_part1[t * 1024 + blockIdx.x] = s1;
    v8_part1[64 * 1024 + t * 1024 + blockIdx.x] = s2;
}

__global__ void v8_bnred1() {
    int o = threadIdx.x;
    float s1 = 0.f, s2 = 0.f;
    for (int i = 0; i < 1024; i++) {
        s1 += v8_part1[o * 1024 + i];
        s2 += v8_part1[64 * 1024 + o * 1024 + i];
    }
    v8_bnp1[o] = s1; v8_bnp1[64 + o] = s2;
}

__global__ void v8_fin1(const float* __restrict__ g, const float* __restrict__ be) {
    int idx = blockIdx.x * blockDim.x + threadIdx.x;
    if (idx >= PTS * 64) return;
    int o = idx & 63;
    float cnt = 327680.0f;
    float mean = v8_bnp1[o] / cnt;
    float var = fmaxf(v8_bnp1[64 + o] / cnt - mean * mean, 0.0f);
    float inv = rsqrtf(var + 1e-5f);
    float gm = g[o];
    float sel = (gm >= 0.f) ? v8_x1max[idx] : v8_x1min[idx];
    float v = (sel - mean) * inv * gm + be[o];
    v8_x1[idx] = fmaxf(v, 0.f);
}

// ----------------------------- e2p (64-dim) + xx2 -----------------------------
__global__ void v8_e2p2() {
    int p = blockIdx.x * 8 + (threadIdx.x >> 5);
    if (p >= PTS) return;
    int lane = threadIdx.x & 31;
    const float* xr = v8_x1 + p * 64;
    float v0 = xr[lane], v1 = xr[lane + 32];
    float s = v0 * v0 + v1 * v1;
    for (int o = 16; o > 0; o >>= 1) s += __shfl_xor_sync(0xffffffffu, s, o);
    if (lane == 0) v8_xx2[p] = s;
    float n = fmaxf(sqrtf(s), 1e-15f);
    float sc = tanhf(SQC * n) / (SQC * n);
    float ny = fmaxf(sc * n, 1e-15f);
    float f = (ny > MAXNORM_F) ? (MAXNORM_F / ny) : 1.0f;
    sc *= f;
    v8_xp2[p * 64 + lane] = v0 * sc;
    v8_xp2[p * 64 + lane + 32] = v1 * sc;
}

// ----------------------------- f32x2 SGEMM core, double-buffered -----------------------------
// Tile 128(M) x 64(N), K-chunk 16, 256 threads, 8x4 microtile (diag/anti-diag FFMA2).
// MODE 0: C = A@B^T             (hc2)
// MODE 2: pd epilogue            (kNN2)
// MODE 3: h2-fused: +hc, BN partial sums per tile, per-point max/min atomics. No C store.
// MODE 5: h3-fused: A = concat(x1,x2), BN partials + per-batch max/min. No C store.
template<int MODE>
static __device__ __forceinline__ float4 v8_loadA(const float* __restrict__ A, int lda,
                                                  int gr, int col) {
    if (MODE == 5) {
        return (col < 64) ? *(const float4*)&v8_x1[(size_t)gr * 64 + col]
                          : *(const float4*)&v8_x2[(size_t)gr * 192 + col - 64];
    }
    return *(const float4*)&A[(size_t)gr * lda + col];
}

template<int MODE>
static __device__ __forceinline__ void v8_gemm_body(
        const float* __restrict__ A, int lda,
        const float* __restrict__ Bw, int ldb,
        float* __restrict__ C, int ldc, int K,
        const float* __restrict__ hc,
        const float* __restrict__ xx) {
    __shared__ __align__(16) float As[16][132];
    __shared__ __align__(16) float BsN[16][68];
    __shared__ __align__(16) float BsS[16][68];
    int tid = threadIdx.x;
    int tx = tid & 15, ty = tid >> 4;
    int m0 = blockIdx.y * 128, n0 = blockIdx.x * 64;
    int lr = tid >> 2, lc = tid & 3;
    unsigned long long accD[4][2], accA2[4][2];
#pragma unroll
    for (int p = 0; p < 4; p++)
#pragma unroll
        for (int q = 0; q < 2; q++) { accD[p][q] = 0ull; accA2[p][q] = 0ull; }

    float4 aR0 = v8_loadA<MODE>(A, lda, m0 + lr, lc * 4);
    float4 aR1 = v8_loadA<MODE>(A, lda, m0 + lr + 64, lc * 4);
    float4 bR = *(const float4*)&Bw[(size_t)(n0 + lr) * ldb + lc * 4];

    for (int k0 = 0; k0 < K; k0 += 16) {
        As[lc * 4 + 0][lr] = aR0.x; As[lc * 4 + 1][lr] = aR0.y;
        As[lc * 4 + 2][lr] = aR0.z; As[lc * 4 + 3][lr] = aR0.w;
        As[lc * 4 + 0][lr + 64] = aR1.x; As[lc * 4 + 1][lr + 64] = aR1.y;
        As[lc * 4 + 2][lr + 64] = aR1.z; As[lc * 4 + 3][lr + 64] = aR1.w;
        BsN[lc * 4 + 0][lr] = bR.x; BsN[lc * 4 + 1][lr] = bR.y;
        BsN[lc * 4 + 2][lr] = bR.z; BsN[lc * 4 + 3][lr] = bR.w;
        int ns = lr ^ 1;
        BsS[lc * 4 + 0][ns] = bR.x; BsS[lc * 4 + 1][ns] = bR.y;
        BsS[lc * 4 + 2][ns] = bR.z; BsS[lc * 4 + 3][ns] = bR.w;
        __syncthreads();
        if (k0 + 16 < K) {
            aR0 = v8_loadA<MODE>(A, lda, m0 + lr, k0 + 16 + lc * 4);
            aR1 = v8_loadA<MODE>(A, lda, m0 + lr + 64, k0 + 16 + lc * 4);
            bR = *(const float4*)&Bw[(size_t)(n0 + lr) * ldb + k0 + 16 + lc * 4];
        }
#pragma unroll
        for (int kk = 0; kk < 16; kk++) {
            ulonglong2 a01 = *(const ulonglong2*)&As[kk][ty * 8];
            ulonglong2 a23 = *(const ulonglong2*)&As[kk][ty * 8 + 4];
            ulonglong2 bn = *(const ulonglong2*)&BsN[kk][tx * 4];
            ulonglong2 bs = *(const ulonglong2*)&BsS[kk][tx * 4];
            unsigned long long A2[4] = {a01.x, a01.y, a23.x, a23.y};
            unsigned long long BN2[2] = {bn.x, bn.y};
            unsigned long long BS2[2] = {bs.x, bs.y};
#pragma unroll
            for (int p = 0; p < 4; p++) {
#pragma unroll
                for (int q = 0; q < 2; q++) {
                    accD[p][q] = v8_fma2(A2[p], BN2[q], accD[p][q]);
                    accA2[p][q] = v8_fma2(A2[p], BS2[q], accA2[p][q]);
                }
            }
        }
        __syncthreads();
    }

    // unpack accumulators: cc[rr][j] for rows m0+ty*8+rr, cols n0+tx*4+j
    float cc[8][4];
#pragma unroll
    for (int p = 0; p < 4; p++) {
#pragma unroll
        for (int q = 0; q < 2; q++) {
            v8_u2f d, a;
            d.u = accD[p][q]; a.u = accA2[p][q];
            cc[2 * p + 0][2 * q + 0] = d.f.x;
            cc[2 * p + 0][2 * q + 1] = a.f.x;
            cc[2 * p + 1][2 * q + 0] = a.f.y;
            cc[2 * p + 1][2 * q + 1] = d.f.y;
        }
    }
    int nb = n0 + tx * 4;
    int rowbase = m0 + ty * 8;

    if (MODE == 0) {
#pragma unroll
        for (int rr = 0; rr < 8; rr++)
            *(float4*)&C[(size_t)(rowbase + rr) * ldc + nb] =
                make_float4(cc[rr][0], cc[rr][1], cc[rr][2], cc[rr][3]);
    }
    if (MODE == 2) {
#pragma unroll
        for (int rr = 0; rr < 8; rr++) {
            float xm = xx[rowbase + rr];
            float4 o4;
            o4.x = (2.0f * cc[rr][0] - xm) - xx[nb + 0];
            o4.y = (2.0f * cc[rr][1] - xm) - xx[nb + 1];
            o4.z = (2.0f * cc[rr][2] - xm) - xx[nb + 2];
            o4.w = (2.0f * cc[rr][3] - xm) - xx[nb + 3];
            *(float4*)&C[(size_t)(rowbase + rr) * ldc + nb] = o4;
        }
    }
    if (MODE == 3) {
        // add hconst per row's point
#pragma unroll
        for (int rr = 0; rr < 8; rr++) {
            int pt = (rowbase + rr) / KNN;
            const float* hp = &hc[(size_t)pt * 192 + nb];
#pragma unroll
            for (int j = 0; j < 4; j++) cc[rr][j] += hp[j];
        }
        // BN partial sums (fixed order)
        float s1[4] = {0.f, 0.f, 0.f, 0.f}, s2[4] = {0.f, 0.f, 0.f, 0.f};
#pragma unroll
        for (int rr = 0; rr < 8; rr++)
#pragma unroll
            for (int j = 0; j < 4; j++) { float v = cc[rr][j]; s1[j] += v; s2[j] += v * v; }
        float* rs1 = &BsS[0][0];
        float* rs2 = &As[0][0];
        int* sMx = (int*)(&As[0][0] + 1088);
        int* sMn = (int*)&BsN[0][0];
#pragma unroll
        for (int j = 0; j < 4; j++) {
            rs1[ty * 68 + tx * 4 + j] = s1[j];
            rs2[ty * 68 + tx * 4 + j] = s2[j];
        }
        for (int i = tid; i < 544; i += 256) { sMx[i] = (int)0x80000000; sMn[i] = 0x7FFFFFFF; }
        __syncthreads();
        // tree-reduce sums over ty
        for (int s = 8; s > 0; s >>= 1) {
            if (ty < s) {
#pragma unroll
                for (int j = 0; j < 4; j++) {
                    rs1[ty * 68 + tx * 4 + j] += rs1[(ty + s) * 68 + tx * 4 + j];
                    rs2[ty * 68 + tx * 4 + j] += rs2[(ty + s) * 68 + tx * 4 + j];
                }
            }
            __syncthreads();
        }
        // per-point max/min into smem (encoded int atomics; commutative => deterministic)
        int firstPt = m0 / KNN;
        {
            int curPt = rowbase / KNN;
            float mx[4], mn[4];
#pragma unroll
            for (int j = 0; j < 4; j++) { mx[j] = cc[0][j]; mn[j] = cc[0][j]; }
#pragma unroll
            for (int rr = 1; rr < 8; rr++) {
                int pt = (rowbase + rr) / KNN;
                if (pt != curPt) {
                    int pl = curPt - firstPt;
#pragma unroll
                    for (int j = 0; j < 4; j++) {
                        atomicMax(&sMx[pl * 68 + tx * 4 + j], v8_fenc(mx[j]));
                        atomicMin(&sMn[pl * 68 + tx * 4 + j], v8_fenc(mn[j]));
                    }
                    curPt = pt;
#pragma unroll
                    for (int j = 0; j < 4; j++) { mx[j] = cc[rr][j]; mn[j] = cc[rr][j]; }
                } else {
#pragma unroll
                    for (int j = 0; j < 4; j++) {
                        mx[j] = fmaxf(mx[j], cc[rr][j]);
                        mn[j] = fminf(mn[j], cc[rr][j]);
                    }
                }
            }
            int pl = curPt - firstPt;
#pragma unroll
            for (int j = 0; j < 4; j++) {
                atomicMax(&sMx[pl * 68 + tx * 4 + j], v8_fenc(mx[j]));
                atomicMin(&sMn[pl * 68 + tx * 4 + j], v8_fenc(mn[j]));
            }
        }
        __syncthreads();
        if (ty == 0) {
#pragma unroll
            for (int j = 0; j < 4; j++) {
                v8_p2s1[(size_t)(nb + j) * H2TILES + blockIdx.y] = rs1[tx * 4 + j];
                v8_p2s2[(size_t)(nb + j) * H2TILES + blockIdx.y] = rs2[tx * 4 + j];
            }
        }
        // flush per-tile point max/min to global
        int lastPt = (m0 + 127) / KNN;
        for (int e = tid; e < 512; e += 256) {
            int pl = e >> 6, col = e & 63;
            int pt = firstPt + pl;
            if (pt <= lastPt) {
                int me = sMx[pl * 68 + col];
                if (me != (int)0x80000000) {
                    atomicMax(&v8_x2maxI[(size_t)pt * 192 + n0 + col], me);
                    atomicMin(&v8_x2minI[(size_t)pt * 192 + n0 + col], sMn[pl * 68 + col]);
                }
            }
        }
    }
    if (MODE == 5) {
        int b = m0 >> 10;
        float s1[4] = {0.f, 0.f, 0.f, 0.f}, s2[4] = {0.f, 0.f, 0.f, 0.f};
        float mx[4], mn[4];
#pragma unroll
        for (int j = 0; j < 4; j++) { mx[j] = cc[0][j]; mn[j] = cc[0][j]; }
#pragma unroll
        for (int rr = 0; rr < 8; rr++)
#pragma unroll
            for (int j = 0; j < 4; j++) {
                float v = cc[rr][j];
                s1[j] += v; s2[j] += v * v;
                if (rr > 0) { mx[j] = fmaxf(mx[j], v); mn[j] = fminf(mn[j], v); }
            }
        float* rs1 = &BsS[0][0];
        float* rs2 = &As[0][0];
        // phase 1: sums
#pragma unroll
        for (int j = 0; j < 4; j++) {
            rs1[ty * 68 + tx * 4 + j] = s1[j];
            rs2[ty * 68 + tx * 4 + j] = s2[j];
        }
        __syncthreads();
        for (int s = 8; s > 0; s >>= 1) {
            if (ty < s) {
#pragma unroll
                for (int j = 0; j < 4; j++) {
                    rs1[ty * 68 + tx * 4 + j] += rs1[(ty + s) * 68 + tx * 4 + j];
                    rs2[ty * 68 + tx * 4 + j] += rs2[(ty + s) * 68 + tx * 4 + j];
                }
            }
            __syncthreads();
        }
        if (ty == 0) {
#pragma unroll
            for (int j = 0; j < 4; j++) {
                v8_p3s1[(size_t)(nb + j) * H3TILES + blockIdx.y] = rs1[tx * 4 + j];
                v8_p3s2[(size_t)(nb + j) * H3TILES + blockIdx.y] = rs2[tx * 4 + j];
            }
        }
        __syncthreads();
        // phase 2: max/min
#pragma unroll
        for (int j = 0; j < 4; j++) {
            rs1[ty * 68 + tx * 4 + j] = mx[j];
            rs2[ty * 68 + tx * 4 + j] = mn[j];
        }
        __syncthreads();
        for (int s = 8; s > 0; s >>= 1) {
            if (ty < s) {
#pragma unroll
                for (int j = 0; j < 4; j++) {
                    rs1[ty * 68 + tx * 4 + j] = fmaxf(rs1[ty * 68 + tx * 4 + j], rs1[(ty + s) * 68 + tx * 4 + j]);
                    rs2[ty * 68 + tx * 4 + j] = fminf(rs2[ty * 68 + tx * 4 + j], rs2[(ty + s) * 68 + tx * 4 + j]);
                }
            }
            __syncthreads();
        }
        if (ty == 0) {
#pragma unroll
            for (int j = 0; j < 4; j++) {
                atomicMax(&v8_c3maxI[b * 1024 + nb + j], v8_fenc(rs1[tx * 4 + j]));
                atomicMin(&v8_c3minI[b * 1024 + nb + j], v8_fenc(rs2[tx * 4 + j]));
            }
        }
    }
}

// hc2[PTS x 192] = xp2 @ w2[:,64:]^T
__global__ void __launch_bounds__(256) v8_gemm_hc2(const float* __restrict__ w2) {
    v8_gemm_body<0>(v8_xp2, 64, w2 + 64, 128, v8_hc2, 192, 64, nullptr, nullptr);
}
// h2 fused: (mob2 @ w2[:,0:64]^T + hc2) -> BN partials + per-point max/min
__global__ void __launch_bounds__(256) v8_gemm_h2(const float* __restrict__ w2) {
    v8_gemm_body<3>(v8_mob2, 64, w2, 128, nullptr, 0, 64, v8_hc2, nullptr);
}
// h3 fused: concat(x1,x2) @ conv3_w^T -> BN partials + per-batch max/min
__global__ void __launch_bounds__(256) v8_gemm_h3(const float* __restrict__ w3) {
    v8_gemm_body<5>(nullptr, 0, w3, 256, nullptr, 0, 256, nullptr, nullptr);
}
// pd[b][m][n] = 2*(x1_b[m].x1_b[n]) - xx[m] - xx[n]
__global__ void __launch_bounds__(256) v8_gemm_pd2() {
    int b = blockIdx.z;
    const float* Xb = v8_x1 + (size_t)b * NPT * 64;
    float* Cb = v8_pd + (size_t)b * NPT * NPT;
    const float* xxb = v8_xx2 + b * NPT;
    v8_gemm_body<2>(Xb, 64, Xb, 64, Cb, NPT, 64, nullptr, xxb);
}

// ----------------------------- mobius edge features, layer 2 -----------------------------
__global__ void v8_mobB() {
    int g = blockIdx.x * 8 + (threadIdx.x >> 5);
    if (g >= NEDGE) return;
    int lane = threadIdx.x & 31;
    int p = g / KNN;
    int jp = v8_idx2[g];
    const float2* fx = (const float2*)(v8_xp2 + (size_t)jp * 64);
    const float2* cx = (const float2*)(v8_xp2 + (size_t)p * 64);
    float2 f = fx[lane], c2 = cx[lane];
    float x2s = f.x * f.x + f.y * f.y;
    float y2 = c2.x * c2.x + c2.y * c2.y;
    float d = f.x * c2.x + f.y * c2.y;
    for (int o = 16; o > 0; o >>= 1) {
        x2s += __shfl_xor_sync(0xffffffffu, x2s, o);
        y2 += __shfl_xor_sync(0xffffffffu, y2, o);
        d += __shfl_xor_sync(0xffffffffu, d, o);
    }
    float A = 1.0f - 0.02f * d + 0.01f * y2;
    float Bc = 1.0f - 0.01f * x2s;
    float den = fmaxf(1.0f - 0.02f * d + 1e-4f * x2s * y2, 1e-15f);
    float r = 1.0f / den;
    float2 o2;
    o2.x = (A * f.x - Bc * c2.x) * r;
    o2.y = (A * f.y - Bc * c2.y) * r;
    ((float2*)(v8_mob2 + (size_t)g * 64))[lane] = o2;
}

// ----------------------------- BN2 partial reduce + finalize -----------------------------
__global__ void v8_bnred2() {
    __shared__ float sA[256], sB[256];
    int o = blockIdx.x, t = threadIdx.x;
    float a = 0.f, b = 0.f;
    for (int i = t; i < H2TILES; i += 256) {
        a += v8_p2s1[(size_t)o * H2TILES + i];
        b += v8_p2s2[(size_t)o * H2TILES + i];
    }
    sA[t] = a; sB[t] = b;
    __syncthreads();
    for (int s = 128; s > 0; s >>= 1) {
        if (t < s) { sA[t] += sA[t + s]; sB[t] += sB[t + s]; }
        __syncthreads();
    }
    if (t == 0) { v8_bnp2[o] = sA[0]; v8_bnp2[192 + o] = sB[0]; }
}

__global__ void v8_fin2(const float* __restrict__ g, const float* __restrict__ be) {
    int idx = blockIdx.x * blockDim.x + threadIdx.x;
    if (idx >= PTS * 192) return;
    int o = idx % 192;
    float cnt = 327680.0f;
    float mean = v8_bnp2[o] / cnt;
    float var = fmaxf(v8_bnp2[192 + o] / cnt - mean * mean, 0.0f);
    float inv = rsqrtf(var + 1e-5f);
    float gm = g[o];
    float sel = (gm >= 0.f) ? v8_fdec(v8_x2maxI[idx]) : v8_fdec(v8_x2minI[idx]);
    float v = (sel - mean) * inv * gm + be[o];
    v8_x2[idx] = fmaxf(v, 0.f);
}

// ----------------------------- BN3 partial reduce + finalize -----------------------------
__global__ void v8_bnred3() {
    __shared__ float sA[128], sB[128];
    int o = blockIdx.x, t = threadIdx.x;
    sA[t] = v8_p3s1[(size_t)o * H3TILES + t];
    sB[t] = v8_p3s2[(size_t)o * H3TILES + t];
    __syncthreads();
    for (int s = 64; s > 0; s >>= 1) {
        if (t < s) { sA[t] += sA[t + s]; sB[t] += sB[t + s]; }
        __syncthreads();
    }
    if (t == 0) { v8_bnp3[o] = sA[0]; v8_bnp3[1024 + o] = sB[0]; }
}

__global__ void v8_fin3(const float* __restrict__ g, const float* __restrict__ be) {
    int idx = blockIdx.x * blockDim.x + threadIdx.x;
    if (idx >= PTS) return;
    int o = idx & 1023;
    float cnt = 16384.0f;
    float mean = v8_bnp3[o] / cnt;
    float var = fmaxf(v8_bnp3[1024 + o] / cnt - mean * mean, 0.0f);
    float inv = rsqrtf(var + 1e-5f);
    float gm = g[o];
    float sel = (gm >= 0.f) ? v8_fdec(v8_c3maxI[idx]) : v8_fdec(v8_c3minI[idx]);
    float v = (sel - mean) * inv * gm + be[o];
    v8_feat3[idx] = fmaxf(v, 0.f);
}

// ----------------------------- head -----------------------------
__global__ void v8_fc1(const float* __restrict__ w, const float* __restrict__ bias,
                       const float* __restrict__ g, const float* __restrict__ be) {
    __shared__ float sIn[1024];
    __shared__ float sOut[512];
    __shared__ float red[256];
    int b = blockIdx.x, t = threadIdx.x;
    for (int i = t; i < 1024; i += 256) sIn[i] = v8_feat3[b * 1024 + i];
    __syncthreads();
    for (int r = 0; r < 2; r++) {
        int o = t + r * 256;
        float acc = bias[o];
        const float* wr = w + (size_t)o * 1024;
        for (int i = 0; i < 1024; i++) acc = fmaf(wr[i], sIn[i], acc);
        sOut[o] = acc;
    }
    __syncthreads();
    red[t] = sOut[t] + sOut[t + 256];
    __syncthreads();
    for (int s = 128; s > 0; s >>= 1) { if (t < s) red[t] += red[t + s]; __syncthreads(); }
    float mean = red[0] / 512.0f;
    __syncthreads();
    float d0 = sOut[t] - mean, d1 = sOut[t + 256] - mean;
    red[t] = d0 * d0 + d1 * d1;
    __syncthreads();
    for (int s = 128; s > 0; s >>= 1) { if (t < s) red[t] += red[t + s]; __syncthreads(); }
    float inv = rsqrtf(red[0] / 512.0f + 1e-5f);
    for (int r = 0; r < 2; r++) {
        int o = t + r * 256;
        float v = (sOut[o] - mean) * inv * g[o] + be[o];
        v8_hf1[b * 512 + o] = fmaxf(v, 0.f);
    }
}

__global__ void v8_fc2(const float* __restrict__ w, const float* __restrict__ bias,
                       const float* __restrict__ g, const float* __restrict__ be) {
    __shared__ float sIn[512];
    __shared__ float sOut[256];
    __shared__ float red[256];
    int b = blockIdx.x, t = threadIdx.x;
    for (int i = t; i < 512; i += 256) sIn[i] = v8_hf1[b * 512 + i];
    __syncthreads();
    {
        float acc = bias[t];
        const float* wr = w + (size_t)t * 512;
        for (int i = 0; i < 512; i++) acc = fmaf(wr[i], sIn[i], acc);
        sOut[t] = acc;
    }
    __syncthreads();
    red[t] = sOut[t];
    __syncthreads();
    for (int s = 128; s > 0; s >>= 1) { if (t < s) red[t] += red[t + s]; __syncthreads(); }
    float mean = red[0] / 256.0f;
    __syncthreads();
    float d0 = sOut[t] - mean;
    red[t] = d0 * d0;
    __syncthreads();
    for (int s = 128; s > 0; s >>= 1) { if (t < s) red[t] += red[t + s]; __syncthreads(); }
    float inv = rsqrtf(red[0] / 256.0f + 1e-5f);
    float v = (sOut[t] - mean) * inv * g[t] + be[t];
    v8_hf2[b * 256 + t] = fmaxf(v, 0.f);
}

__global__ void v8_outp(const float* __restrict__ w, const float* __restrict__ bias,
                        float* __restrict__ out) {
    __shared__ float sIn[256];
    __shared__ float lg[40];
    __shared__ float mS, lS;
    int b = blockIdx.x, t = threadIdx.x;
    for (int i = t; i < 256; i += 64) sIn[i] = v8_hf2[b * 256 + i];
    __syncthreads();
    if (t < 40) {
        float acc = bias[t];
        const float* wr = w + (size_t)t * 256;
        for (int i = 0; i < 256; i++) acc = fmaf(wr[i], sIn[i], acc);
        lg[t] = acc;
    }
    __syncthreads();
    if (t == 0) {
        float m = NEG_INF;
        for (int i = 0; i < 40; i++) m = fmaxf(m, lg[i]);
        float s = 0.f;
        for (int i = 0; i < 40; i++) s += expf(lg[i] - m);
        mS = m; lS = logf(s);
    }
    __syncthreads();
    if (t < 40) out[b * 40 + t] = lg[t] - mS - lS;
}

// ----------------------------- launch -----------------------------
extern "C" void kernel_launch(void* const* d_in, const int* in_sizes, int n_in,
                              void* d_out, int out_size) {
    const float* x       = (const float*)d_in[0];
    const float* conv1_w = (const float*)d_in[1];
    const float* bn1_g   = (const float*)d_in[2];
    const float* bn1_b   = (const float*)d_in[3];
    const float* conv2_w = (const float*)d_in[4];
    const float* bn2_g   = (const float*)d_in[5];
    const float* bn2_b   = (const float*)d_in[6];
    const float* conv3_w = (const float*)d_in[7];
    const float* bn3_g   = (const float*)d_in[8];
    const float* bn3_b   = (const float*)d_in[9];
    const float* fc1_w   = (const float*)d_in[10];
    const float* fc1_b   = (const float*)d_in[11];
    const float* ln1_g   = (const float*)d_in[12];
    const float* ln1_b   = (const float*)d_in[13];
    const float* fc2_w   = (const float*)d_in[14];
    const float* fc2_b   = (const float*)d_in[15];
    const float* ln2_g   = (const float*)d_in[16];
    const float* ln2_b   = (const float*)d_in[17];
    const float* out_w   = (const float*)d_in[18];
    const float* out_b   = (const float*)d_in[19];
    float* out = (float*)d_out;

    v8_init<<<12288, 256>>>();

    // stage 1
    v8_e2p1<<<64, 256>>>(x);
    v8_pd1<<<PTS, 256>>>(x);
    v8_topk<<<PTS, 256>>>(0);
    v8_mobA<<<(NEDGE + 255) / 256, 256>>>();
    v8_conv1<<<1024, 64>>>(conv1_w);
    v8_bnred1<<<1, 64>>>();
    v8_fin1<<<(PTS * 64) / 256, 256>>>(bn1_g, bn1_b);

    // stage 2
    v8_e2p2<<<PTS / 8, 256>>>();
    v8_gemm_pd2<<<dim3(16, 8, 16), 256>>>();
    v8_topk<<<PTS, 256>>>(1);
    v8_gemm_hc2<<<dim3(3, PTS / 128), 256>>>(conv2_w);
    v8_mobB<<<NEDGE / 8, 256>>>();
    v8_gemm_h2<<<dim3(3, H2TILES), 256>>>(conv2_w);
    v8_bnred2<<<192, 256>>>();
    v8_fin2<<<(PTS * 192) / 256, 256>>>(bn2_g, bn2_b);

    // stage 3 (concat folded into h3 A-load)
    v8_gemm_h3<<<dim3(16, H3TILES), 256>>>(conv3_w);
    v8_bnred3<<<1024, 128>>>();
    v8_fin3<<<PTS / 256, 256>>>(bn3_g, bn3_b);

    // head
    v8_fc1<<<BBATCH, 256>>>(fc1_w, fc1_b, ln1_g, ln1_b);
    v8_fc2<<<BBATCH, 256>>>(fc2_w, fc2_b, ln2_g, ln2_b);
    v8_outp<<<BBATCH, 64>>>(out_w, out_b, out);
}